// round 7
// baseline (speedup 1.0000x reference)
#include <cuda_runtime.h>
#include <cuda_bf16.h>
#include <math.h>

#define B_    2
#define NH_   4
#define T_    8
#define H_    14
#define W_    14
#define N_    1568
#define DIM_  384
#define HD_   96
#define BH_   (B_*NH_)
#define M_    (B_*N_)
#define EPS_  1e-6f
#define SCALE_ 0.1020620726159657f   // 96^-0.5

typedef unsigned long long ull;

// ---- packed f32x2 helpers (FFMA2: PTX-only) ------------------------------
__device__ __forceinline__ void fma2(ull& d, ull a, ull b) {
    asm("fma.rn.f32x2 %0, %1, %2, %0;" : "+l"(d) : "l"(a), "l"(b));
}
__device__ __forceinline__ float hadd2(ull v) {
    float lo, hi;
    asm("mov.b64 {%0, %1}, %2;" : "=f"(lo), "=f"(hi) : "l"(v));
    return lo + hi;
}
__device__ __forceinline__ ull dup2(float f) {
    ull d;
    asm("mov.b64 %0, {%1, %1};" : "=l"(d) : "f"(f));
    return d;
}
__device__ __forceinline__ void unpack2(ull v, float& lo, float& hi) {
    asm("mov.b64 {%0, %1}, %2;" : "=f"(lo), "=f"(hi) : "l"(v));
}

// ---------------- scratch ---------------------------------------------------
__device__ float g_q_raw[BH_ * N_ * HD_];
__device__ float g_k_raw[BH_ * N_ * HD_];
__device__ float g_v_raw[BH_ * N_ * HD_];
__device__ float g_q[BH_ * N_ * HD_];
__device__ float g_k[BH_ * N_ * HD_];
__device__ float g_v[BH_ * N_ * HD_];
__device__ float g_ctx[B_ * N_ * DIM_];

// ------- 64x64 NT GEMM core, packed-k FFMA2, double-buffered smem ----------
__device__ __forceinline__ void gemm_nt64(const float* __restrict__ A,
                                          const float* __restrict__ Bw,
                                          int K, int m0, int n0,
                                          int xx, int yy, ull acc2[4][4]) {
    __shared__ float Xs[2][64 * 36];
    __shared__ float Ws[2][64 * 36];
    const int tid = yy * 16 + xx;
    const int r0 = tid >> 3, c40 = tid & 7;
    const int r1 = (tid + 256) >> 3, c41 = tid & 7;

    // preload tile 0
    float4 pa0 = *(const float4*)&A[(size_t)(m0 + r0) * K + c40 * 4];
    float4 pb0 = *(const float4*)&Bw[(size_t)(n0 + r0) * K + c40 * 4];
    float4 pa1 = *(const float4*)&A[(size_t)(m0 + r1) * K + c41 * 4];
    float4 pb1 = *(const float4*)&Bw[(size_t)(n0 + r1) * K + c41 * 4];
    *(float4*)&Xs[0][r0 * 36 + c40 * 4] = pa0;
    *(float4*)&Ws[0][r0 * 36 + c40 * 4] = pb0;
    *(float4*)&Xs[0][r1 * 36 + c41 * 4] = pa1;
    *(float4*)&Ws[0][r1 * 36 + c41 * 4] = pb1;
    __syncthreads();

    int p = 0;
    for (int k0 = 0; k0 < K; k0 += 32) {
        // prefetch next tile into regs (overlaps with compute below)
        if (k0 + 32 < K) {
            pa0 = *(const float4*)&A[(size_t)(m0 + r0) * K + k0 + 32 + c40 * 4];
            pb0 = *(const float4*)&Bw[(size_t)(n0 + r0) * K + k0 + 32 + c40 * 4];
            pa1 = *(const float4*)&A[(size_t)(m0 + r1) * K + k0 + 32 + c41 * 4];
            pb1 = *(const float4*)&Bw[(size_t)(n0 + r1) * K + k0 + 32 + c41 * 4];
        }
        #pragma unroll
        for (int c4 = 0; c4 < 8; c4++) {
            ulonglong2 a[4];
            #pragma unroll
            for (int rr = 0; rr < 4; rr++)
                a[rr] = *(ulonglong2*)&Xs[p][(yy + 16 * rr) * 36 + c4 * 4];
            #pragma unroll
            for (int u = 0; u < 4; u++) {
                ulonglong2 b = *(ulonglong2*)&Ws[p][(xx + 16 * u) * 36 + c4 * 4];
                #pragma unroll
                for (int rr = 0; rr < 4; rr++) {
                    fma2(acc2[rr][u], a[rr].x, b.x);
                    fma2(acc2[rr][u], a[rr].y, b.y);
                }
            }
        }
        if (k0 + 32 < K) {
            *(float4*)&Xs[1 - p][r0 * 36 + c40 * 4] = pa0;
            *(float4*)&Ws[1 - p][r0 * 36 + c40 * 4] = pb0;
            *(float4*)&Xs[1 - p][r1 * 36 + c41 * 4] = pa1;
            *(float4*)&Ws[1 - p][r1 * 36 + c41 * 4] = pb1;
            __syncthreads();
            p ^= 1;
        }
    }
}

// ---------------- K1: QKV projection ---------------------------------------
__global__ void __launch_bounds__(256, 2) k_qkv(const float* __restrict__ x,
                                                const float* __restrict__ qkv_w) {
    int n0 = blockIdx.x * 64, m0 = blockIdx.y * 64;
    int xx = threadIdx.x & 15, yy = threadIdx.x >> 4;
    ull acc2[4][4] = {};
    gemm_nt64(x, qkv_w, DIM_, m0, n0, xx, yy, acc2);
    #pragma unroll
    for (int rr = 0; rr < 4; rr++) {
        int m = m0 + yy + 16 * rr;
        int b = m / N_, n = m - b * N_;
        #pragma unroll
        for (int u = 0; u < 4; u++) {
            int o = n0 + xx + 16 * u;
            int s = o / DIM_;
            int rem = o - s * DIM_;
            int head = rem / HD_;
            int c = rem - head * HD_;
            float* dst = (s == 0) ? g_q_raw : (s == 1) ? g_k_raw : g_v_raw;
            dst[((size_t)(b * NH_ + head) * N_ + n) * HD_ + c] = hadd2(acc2[rr][u]);
        }
    }
}

// ---------------- K2: conv3x3x3 + LayerNorm, warp per token ---------------
__global__ void __launch_bounds__(128) k_conv_ln(
        const float* __restrict__ wq, const float* __restrict__ wk,
        const float* __restrict__ wv,
        const float* __restrict__ gq, const float* __restrict__ bq,
        const float* __restrict__ gk, const float* __restrict__ bk,
        const float* __restrict__ gv, const float* __restrict__ bv) {
    int gid = blockIdx.x * 4 + (threadIdx.x >> 5);
    int lane = threadIdx.x & 31;
    int z = gid / (BH_ * N_);
    int rem0 = gid - z * (BH_ * N_);
    int bh = rem0 / N_;
    int n = rem0 - bh * N_;
    const float* inb  = (z == 0) ? g_q_raw : (z == 1) ? g_k_raw : g_v_raw;
    float*       outb = (z == 0) ? g_q     : (z == 1) ? g_k     : g_v;
    const float* wt    = (z == 0) ? wq : (z == 1) ? wk : wv;
    const float* gamma = (z == 0) ? gq : (z == 1) ? gk : gv;
    const float* beta  = (z == 0) ? bq : (z == 1) ? bk : bv;

    int tt = n / (H_ * W_);
    int rem = n - tt * (H_ * W_);
    int hh = rem / W_, ww = rem - (rem / W_) * W_;

    float val[3] = {0.f, 0.f, 0.f};
    #pragma unroll
    for (int dt = -1; dt <= 1; dt++) {
        int t2 = tt + dt;
        if (t2 < 0 || t2 >= T_) continue;
        #pragma unroll
        for (int dh = -1; dh <= 1; dh++) {
            int h2 = hh + dh;
            if (h2 < 0 || h2 >= H_) continue;
            #pragma unroll
            for (int dw = -1; dw <= 1; dw++) {
                int w2 = ww + dw;
                if (w2 < 0 || w2 >= W_) continue;
                int n2 = (t2 * H_ + h2) * W_ + w2;
                const float* src = &inb[((size_t)bh * N_ + n2) * HD_];
                int tap = (dt + 1) * 9 + (dh + 1) * 3 + (dw + 1);
                #pragma unroll
                for (int p = 0; p < 3; p++) {
                    int c = lane + 32 * p;
                    val[p] += wt[c * 27 + tap] * src[c];
                }
            }
        }
    }
    float s = val[0] + val[1] + val[2];
    float q = val[0]*val[0] + val[1]*val[1] + val[2]*val[2];
    #pragma unroll
    for (int o = 16; o; o >>= 1) {
        s += __shfl_xor_sync(0xffffffffu, s, o);
        q += __shfl_xor_sync(0xffffffffu, q, o);
    }
    float mean = s * (1.f / HD_);
    float var  = q * (1.f / HD_) - mean * mean;
    float rstd = rsqrtf(var + EPS_);
    float* dst = &outb[((size_t)bh * N_ + n) * HD_];
    #pragma unroll
    for (int p = 0; p < 3; p++) {
        int c = lane + 32 * p;
        dst[c] = (val[p] - mean) * rstd * gamma[c] + beta[c];
    }
}

// ---------------- K3: flash attention, 64-row tiles, R=4, FFMA2 ------------
// grid (25, 8). 64 Q rows/block, 64-key chunks. No-max softmax (bounded
// scores from LN'd q/k). 256 thr: rows y+16rr (rr<4), S cols x+16u.
__global__ void __launch_bounds__(256, 2) k_flash(const float* __restrict__ rph,
                                                  const float* __restrict__ rpw,
                                                  const float* __restrict__ rpt) {
    extern __shared__ float sm[];
    float* Qs = sm;            // [64][96]   24576B
    float* Ks = sm + 6144;     // [64][100]  (pre-scaled)
    float* Vs = sm + 12544;    // [64][96]
    float* Ps = sm + 18688;    // [64][68]
    float* Rh = sm + 23040;    // [64][14]
    float* Rw = sm + 23936;    // [64][14]
    float* Rt = sm + 24832;    // [64][8]    -> total 25344 floats = 101376B

    int bh = blockIdx.y;
    int i0 = blockIdx.x * 64;
    int tid = threadIdx.x;
    int x = tid & 15, y = tid >> 4;

    const float* Qg = g_q + ((size_t)bh * N_ + i0) * HD_;
    #pragma unroll
    for (int it = 0; it < 6; it++) {
        int idx = tid + 256 * it;            // 1536 = 64 rows x 24 float4
        int r = idx / 24, c4 = idx % 24;
        float4 qv = make_float4(0.f, 0.f, 0.f, 0.f);
        if (i0 + r < N_) qv = *(const float4*)&Qg[r * 96 + c4 * 4];
        *(float4*)&Qs[r * 96 + c4 * 4] = qv;
    }
    __syncthreads();

    // ---- rel-pos bias dots from Qs ----
    #pragma unroll
    for (int idx = tid; idx < 2304; idx += 256) {
        int r = idx / 36, e = idx - (idx / 36) * 36;
        int i = i0 + r;
        const float* tab = rph;   // dummy init
        float* dst;
        bool valid = (i < N_);
        int it = i / 196;
        int rm = i - it * 196;
        int ih = rm / 14, iw = rm - ih * 14;
        if (e < 14)      { tab = rph + (ih - e + 13) * HD_;        dst = &Rh[r * 14 + e]; }
        else if (e < 28) { int k = e - 14; tab = rpw + (iw - k + 13) * HD_; dst = &Rw[r * 14 + k]; }
        else             { int k = e - 28; tab = rpt + (it - k + 7) * HD_;  dst = &Rt[r * 8 + k]; }
        float s = 0.f;
        if (valid) {
            #pragma unroll 6
            for (int c4 = 0; c4 < 24; c4++) {
                float4 a = *(float4*)&Qs[r * 96 + c4 * 4];
                float4 b = *(const float4*)&tab[c4 * 4];
                s += a.x * b.x + a.y * b.y + a.z * b.z + a.w * b.w;
            }
        }
        *dst = s;
    }

    float lpart[4] = {0.f, 0.f, 0.f, 0.f};
    ull accO2[4][3] = {};

    const float* Kg = g_k + (size_t)bh * N_ * HD_;
    const float* Vg = g_v + (size_t)bh * N_ * HD_;

    for (int ch = 0; ch < 25; ch++) {
        int j0 = ch * 64;
        __syncthreads();
        #pragma unroll
        for (int it = 0; it < 6; it++) {
            int idx = tid + 256 * it;        // 1536 = 64 rows x 24 float4
            int row = idx / 24, c4 = idx % 24;
            int j = j0 + row;
            float4 kv, vv;
            if (j < N_) {
                kv = *(const float4*)&Kg[(size_t)j * 96 + c4 * 4];
                vv = *(const float4*)&Vg[(size_t)j * 96 + c4 * 4];
            } else {
                kv = make_float4(0.f, 0.f, 0.f, 0.f);
                vv = kv;
            }
            kv.x *= SCALE_; kv.y *= SCALE_; kv.z *= SCALE_; kv.w *= SCALE_;
            *(float4*)&Ks[row * 100 + c4 * 4] = kv;
            *(float4*)&Vs[row * 96  + c4 * 4] = vv;
        }
        __syncthreads();

        // ---- GEMM1: S = Q @ (K*scale)^T (packed along k) ----
        ull accS2[4][4] = {};
        #pragma unroll 6
        for (int c4 = 0; c4 < 24; c4++) {
            ulonglong2 a[4];
            #pragma unroll
            for (int rr = 0; rr < 4; rr++)
                a[rr] = *(ulonglong2*)&Qs[(y + 16 * rr) * 96 + c4 * 4];
            #pragma unroll
            for (int u = 0; u < 4; u++) {
                ulonglong2 b = *(ulonglong2*)&Ks[(x + 16 * u) * 100 + c4 * 4];
                #pragma unroll
                for (int rr = 0; rr < 4; rr++) {
                    fma2(accS2[rr][u], a[rr].x, b.x);
                    fma2(accS2[rr][u], a[rr].y, b.y);
                }
            }
        }

        // ---- bias + exp (no max subtraction; bounded scores) ----
        #pragma unroll
        for (int rr = 0; rr < 4; rr++) {
            int r = y + 16 * rr;
            #pragma unroll
            for (int u = 0; u < 4; u++) {
                int j = j0 + x + 16 * u;
                float p = 0.f;
                if (j < N_) {
                    int jt = j / 196;
                    int jr = j - jt * 196;
                    int jh = jr / 14;
                    int jw = jr - jh * 14;
                    float s = hadd2(accS2[rr][u])
                            + Rt[r * 8 + jt] + Rh[r * 14 + jh] + Rw[r * 14 + jw];
                    p = __expf(s);
                }
                lpart[rr] += p;
                Ps[r * 68 + x + 16 * u] = p;
            }
        }
        __syncthreads();

        // ---- GEMM2: O += P @ V (packed along output cols) ----
        #pragma unroll 4
        for (int j4 = 0; j4 < 16; j4++) {
            float4 p[4];
            #pragma unroll
            for (int rr = 0; rr < 4; rr++)
                p[rr] = *(float4*)&Ps[(y + 16 * rr) * 68 + j4 * 4];
            #pragma unroll
            for (int jj = 0; jj < 4; jj++) {
                const float* vb = &Vs[(j4 * 4 + jj) * 96 + x * 6];
                ull v0 = *(const ull*)(vb + 0);
                ull v1 = *(const ull*)(vb + 2);
                ull v2 = *(const ull*)(vb + 4);
                #pragma unroll
                for (int rr = 0; rr < 4; rr++) {
                    float pv = (jj == 0) ? p[rr].x : (jj == 1) ? p[rr].y
                             : (jj == 2) ? p[rr].z : p[rr].w;
                    ull pd = dup2(pv);
                    fma2(accO2[rr][0], pd, v0);
                    fma2(accO2[rr][1], pd, v1);
                    fma2(accO2[rr][2], pd, v2);
                }
            }
        }
    }

    // ---- epilogue: single l-reduction, O/l + residual q -> g_ctx ----
    #pragma unroll
    for (int rr = 0; rr < 4; rr++)
        #pragma unroll
        for (int o = 8; o; o >>= 1)
            lpart[rr] += __shfl_xor_sync(0xffffffffu, lpart[rr], o);

    int b = bh >> 2, nh = bh & 3;
    #pragma unroll
    for (int rr = 0; rr < 4; rr++) {
        int r = y + 16 * rr;
        int i = i0 + r;
        if (i >= N_) continue;
        float inv = 1.f / lpart[rr];
        float* dst = &g_ctx[(((size_t)b * N_ + i) * NH_ + nh) * HD_ + x * 6];
        const float* qrow = &Qs[r * 96 + x * 6];
        #pragma unroll
        for (int tp = 0; tp < 3; tp++) {
            float lo, hi;
            unpack2(accO2[rr][tp], lo, hi);
            dst[2 * tp + 0] = lo * inv + qrow[2 * tp + 0];
            dst[2 * tp + 1] = hi * inv + qrow[2 * tp + 1];
        }
    }
}

// ---------------- K4: output projection + bias -----------------------------
__global__ void __launch_bounds__(256, 2) k_proj(const float* __restrict__ proj_w,
                                                 const float* __restrict__ proj_b,
                                                 float* __restrict__ out) {
    int n0 = blockIdx.x * 64, m0 = blockIdx.y * 64;
    int xx = threadIdx.x & 15, yy = threadIdx.x >> 4;
    ull acc2[4][4] = {};
    gemm_nt64(g_ctx, proj_w, DIM_, m0, n0, xx, yy, acc2);
    #pragma unroll
    for (int rr = 0; rr < 4; rr++) {
        int m = m0 + yy + 16 * rr;
        #pragma unroll
        for (int u = 0; u < 4; u++) {
            int o = n0 + xx + 16 * u;
            out[(size_t)m * DIM_ + o] = hadd2(acc2[rr][u]) + proj_b[o];
        }
    }
}

// ---------------- launch ----------------------------------------------------
extern "C" void kernel_launch(void* const* d_in, const int* in_sizes, int n_in,
                              void* d_out, int out_size) {
    const float* x      = (const float*)d_in[0];
    const float* qkv_w  = (const float*)d_in[1];
    const float* proj_w = (const float*)d_in[2];
    const float* proj_b = (const float*)d_in[3];
    const float* pqw    = (const float*)d_in[4];
    const float* pkw    = (const float*)d_in[5];
    const float* pvw    = (const float*)d_in[6];
    const float* nqw    = (const float*)d_in[7];
    const float* nqb    = (const float*)d_in[8];
    const float* nkw    = (const float*)d_in[9];
    const float* nkb    = (const float*)d_in[10];
    const float* nvw    = (const float*)d_in[11];
    const float* nvb    = (const float*)d_in[12];
    const float* rph    = (const float*)d_in[13];
    const float* rpw    = (const float*)d_in[14];
    const float* rpt    = (const float*)d_in[15];
    float* out = (float*)d_out;

    cudaFuncSetAttribute(k_flash, cudaFuncAttributeMaxDynamicSharedMemorySize, 101376);

    k_qkv<<<dim3(18, 49), 256>>>(x, qkv_w);
    k_conv_ln<<<(BH_ * N_ * 3) / 4, 128>>>(pqw, pkw, pvw, nqw, nqb, nkw, nkb, nvw, nvb);
    k_flash<<<dim3(25, BH_), 256, 101376>>>(rph, rpw, rpt);
    k_proj<<<dim3(6, 49), 256>>>(proj_w, proj_b, out);
}

// round 8
// speedup vs baseline: 1.1837x; 1.1837x over previous
#include <cuda_runtime.h>
#include <cuda_bf16.h>
#include <math.h>

#define B_    2
#define NH_   4
#define T_    8
#define H_    14
#define W_    14
#define N_    1568
#define DIM_  384
#define HD_   96
#define BH_   (B_*NH_)
#define M_    (B_*N_)
#define EPS_  1e-6f
#define SCALE_ 0.1020620726159657f   // 96^-0.5

typedef unsigned long long ull;

// ---- packed f32x2 helpers (FFMA2: PTX-only) ------------------------------
__device__ __forceinline__ void fma2(ull& d, ull a, ull b) {
    asm("fma.rn.f32x2 %0, %1, %2, %0;" : "+l"(d) : "l"(a), "l"(b));
}
__device__ __forceinline__ float hadd2(ull v) {
    float lo, hi;
    asm("mov.b64 {%0, %1}, %2;" : "=f"(lo), "=f"(hi) : "l"(v));
    return lo + hi;
}
__device__ __forceinline__ ull dup2(float f) {
    ull d;
    asm("mov.b64 %0, {%1, %1};" : "=l"(d) : "f"(f));
    return d;
}
__device__ __forceinline__ void unpack2(ull v, float& lo, float& hi) {
    asm("mov.b64 {%0, %1}, %2;" : "=f"(lo), "=f"(hi) : "l"(v));
}
__device__ __forceinline__ unsigned cvt_tf32(float f) {
    unsigned r;
    asm("cvt.rna.tf32.f32 %0, %1;" : "=r"(r) : "f"(f));
    return r;
}
// tf32 mma m16n8k8: D += A*B, A row-major 16x8, B "col" (i.e. [n][k]) 8x8
__device__ __forceinline__ void mma_tf32(float c[4], unsigned a0, unsigned a1,
                                         unsigned a2, unsigned a3,
                                         unsigned b0, unsigned b1) {
    asm("mma.sync.aligned.m16n8k8.row.col.f32.tf32.tf32.f32 "
        "{%0,%1,%2,%3}, {%4,%5,%6,%7}, {%8,%9}, {%0,%1,%2,%3};"
        : "+f"(c[0]), "+f"(c[1]), "+f"(c[2]), "+f"(c[3])
        : "r"(a0), "r"(a1), "r"(a2), "r"(a3), "r"(b0), "r"(b1));
}

// ---------------- scratch ---------------------------------------------------
__device__ float g_q_raw[BH_ * N_ * HD_];
__device__ float g_k_raw[BH_ * N_ * HD_];
__device__ float g_v_raw[BH_ * N_ * HD_];
__device__ float g_q[BH_ * N_ * HD_];
__device__ float g_k[BH_ * N_ * HD_];
__device__ float g_v[BH_ * N_ * HD_];
__device__ float g_ctx[B_ * N_ * DIM_];

// ------- 64x64 NT GEMM core, packed-k FFMA2, double-buffered smem ----------
__device__ __forceinline__ void gemm_nt64(const float* __restrict__ A,
                                          const float* __restrict__ Bw,
                                          int K, int m0, int n0,
                                          int xx, int yy, ull acc2[4][4]) {
    __shared__ float Xs[2][64 * 36];
    __shared__ float Ws[2][64 * 36];
    const int tid = yy * 16 + xx;
    const int r0 = tid >> 3, c40 = tid & 7;
    const int r1 = (tid + 256) >> 3, c41 = tid & 7;

    float4 pa0 = *(const float4*)&A[(size_t)(m0 + r0) * K + c40 * 4];
    float4 pb0 = *(const float4*)&Bw[(size_t)(n0 + r0) * K + c40 * 4];
    float4 pa1 = *(const float4*)&A[(size_t)(m0 + r1) * K + c41 * 4];
    float4 pb1 = *(const float4*)&Bw[(size_t)(n0 + r1) * K + c41 * 4];
    *(float4*)&Xs[0][r0 * 36 + c40 * 4] = pa0;
    *(float4*)&Ws[0][r0 * 36 + c40 * 4] = pb0;
    *(float4*)&Xs[0][r1 * 36 + c41 * 4] = pa1;
    *(float4*)&Ws[0][r1 * 36 + c41 * 4] = pb1;
    __syncthreads();

    int p = 0;
    for (int k0 = 0; k0 < K; k0 += 32) {
        if (k0 + 32 < K) {
            pa0 = *(const float4*)&A[(size_t)(m0 + r0) * K + k0 + 32 + c40 * 4];
            pb0 = *(const float4*)&Bw[(size_t)(n0 + r0) * K + k0 + 32 + c40 * 4];
            pa1 = *(const float4*)&A[(size_t)(m0 + r1) * K + k0 + 32 + c41 * 4];
            pb1 = *(const float4*)&Bw[(size_t)(n0 + r1) * K + k0 + 32 + c41 * 4];
        }
        #pragma unroll
        for (int c4 = 0; c4 < 8; c4++) {
            ulonglong2 a[4];
            #pragma unroll
            for (int rr = 0; rr < 4; rr++)
                a[rr] = *(ulonglong2*)&Xs[p][(yy + 16 * rr) * 36 + c4 * 4];
            #pragma unroll
            for (int u = 0; u < 4; u++) {
                ulonglong2 b = *(ulonglong2*)&Ws[p][(xx + 16 * u) * 36 + c4 * 4];
                #pragma unroll
                for (int rr = 0; rr < 4; rr++) {
                    fma2(acc2[rr][u], a[rr].x, b.x);
                    fma2(acc2[rr][u], a[rr].y, b.y);
                }
            }
        }
        if (k0 + 32 < K) {
            *(float4*)&Xs[1 - p][r0 * 36 + c40 * 4] = pa0;
            *(float4*)&Ws[1 - p][r0 * 36 + c40 * 4] = pb0;
            *(float4*)&Xs[1 - p][r1 * 36 + c41 * 4] = pa1;
            *(float4*)&Ws[1 - p][r1 * 36 + c41 * 4] = pb1;
            __syncthreads();
            p ^= 1;
        }
    }
}

// ---------------- K1: QKV projection ---------------------------------------
__global__ void __launch_bounds__(256, 2) k_qkv(const float* __restrict__ x,
                                                const float* __restrict__ qkv_w) {
    int n0 = blockIdx.x * 64, m0 = blockIdx.y * 64;
    int xx = threadIdx.x & 15, yy = threadIdx.x >> 4;
    ull acc2[4][4] = {};
    gemm_nt64(x, qkv_w, DIM_, m0, n0, xx, yy, acc2);
    #pragma unroll
    for (int rr = 0; rr < 4; rr++) {
        int m = m0 + yy + 16 * rr;
        int b = m / N_, n = m - b * N_;
        #pragma unroll
        for (int u = 0; u < 4; u++) {
            int o = n0 + xx + 16 * u;
            int s = o / DIM_;
            int rem = o - s * DIM_;
            int head = rem / HD_;
            int c = rem - head * HD_;
            float* dst = (s == 0) ? g_q_raw : (s == 1) ? g_k_raw : g_v_raw;
            dst[((size_t)(b * NH_ + head) * N_ + n) * HD_ + c] = hadd2(acc2[rr][u]);
        }
    }
}

// ---------------- K2: conv3x3x3 + LayerNorm, warp per token ---------------
__global__ void __launch_bounds__(128) k_conv_ln(
        const float* __restrict__ wq, const float* __restrict__ wk,
        const float* __restrict__ wv,
        const float* __restrict__ gq, const float* __restrict__ bq,
        const float* __restrict__ gk, const float* __restrict__ bk,
        const float* __restrict__ gv, const float* __restrict__ bv) {
    int gid = blockIdx.x * 4 + (threadIdx.x >> 5);
    int lane = threadIdx.x & 31;
    int z = gid / (BH_ * N_);
    int rem0 = gid - z * (BH_ * N_);
    int bh = rem0 / N_;
    int n = rem0 - bh * N_;
    const float* inb  = (z == 0) ? g_q_raw : (z == 1) ? g_k_raw : g_v_raw;
    float*       outb = (z == 0) ? g_q     : (z == 1) ? g_k     : g_v;
    const float* wt    = (z == 0) ? wq : (z == 1) ? wk : wv;
    const float* gamma = (z == 0) ? gq : (z == 1) ? gk : gv;
    const float* beta  = (z == 0) ? bq : (z == 1) ? bk : bv;

    int tt = n / (H_ * W_);
    int rem = n - tt * (H_ * W_);
    int hh = rem / W_, ww = rem - (rem / W_) * W_;

    float val[3] = {0.f, 0.f, 0.f};
    #pragma unroll
    for (int dt = -1; dt <= 1; dt++) {
        int t2 = tt + dt;
        if (t2 < 0 || t2 >= T_) continue;
        #pragma unroll
        for (int dh = -1; dh <= 1; dh++) {
            int h2 = hh + dh;
            if (h2 < 0 || h2 >= H_) continue;
            #pragma unroll
            for (int dw = -1; dw <= 1; dw++) {
                int w2 = ww + dw;
                if (w2 < 0 || w2 >= W_) continue;
                int n2 = (t2 * H_ + h2) * W_ + w2;
                const float* src = &inb[((size_t)bh * N_ + n2) * HD_];
                int tap = (dt + 1) * 9 + (dh + 1) * 3 + (dw + 1);
                #pragma unroll
                for (int p = 0; p < 3; p++) {
                    int c = lane + 32 * p;
                    val[p] += wt[c * 27 + tap] * src[c];
                }
            }
        }
    }
    float s = val[0] + val[1] + val[2];
    float q = val[0]*val[0] + val[1]*val[1] + val[2]*val[2];
    #pragma unroll
    for (int o = 16; o; o >>= 1) {
        s += __shfl_xor_sync(0xffffffffu, s, o);
        q += __shfl_xor_sync(0xffffffffu, q, o);
    }
    float mean = s * (1.f / HD_);
    float var  = q * (1.f / HD_) - mean * mean;
    float rstd = rsqrtf(var + EPS_);
    float* dst = &outb[((size_t)bh * N_ + n) * HD_];
    #pragma unroll
    for (int p = 0; p < 3; p++) {
        int c = lane + 32 * p;
        dst[c] = (val[p] - mean) * rstd * gamma[c] + beta[c];
    }
}

// ---------------- K3: flash attention, tf32 MMA for QK^T -------------------
// grid (25, 8). 64 Q rows x 64-key chunks. GEMM1 = tf32 mma.sync (8 warps as
// 4m x 2n, warp tile 16x32). exp/bias in C-fragment layout; P stored fp32;
// GEMM2 (P@V) stays FFMA2. No-max softmax (LN-bounded scores).
__global__ void __launch_bounds__(256, 2) k_flash(const float* __restrict__ rph,
                                                  const float* __restrict__ rpw,
                                                  const float* __restrict__ rpt) {
    extern __shared__ float sm[];
    float* Qs = sm;            // [64][100]  (full fp32; residual needs exact q)
    float* Ks = sm + 6400;     // [64][100]  (tf32-rounded, pre-scaled)
    float* Vs = sm + 12800;    // [64][96]
    float* Ps = sm + 18944;    // [64][68]
    float* Rh = sm + 23296;    // [64][14]
    float* Rw = sm + 24192;    // [64][14]
    float* Rt = sm + 25088;    // [64][8]
    float* Ls = sm + 25600;    // [64][2] row-sum partials per n-warp
    // total 25728 floats = 102912 B

    int bh = blockIdx.y;
    int i0 = blockIdx.x * 64;
    int tid = threadIdx.x;
    int x = tid & 15, y = tid >> 4;           // GEMM2 / epilogue layout
    int wid = tid >> 5, lane = tid & 31;      // MMA layout
    int wm = wid >> 1, wn = wid & 1;
    int g = lane >> 2, t = lane & 3;

    const float* Qg = g_q + ((size_t)bh * N_ + i0) * HD_;
    #pragma unroll
    for (int it = 0; it < 6; it++) {
        int idx = tid + 256 * it;            // 1536 = 64 rows x 24 float4
        int r = idx / 24, c4 = idx % 24;
        float4 qv = make_float4(0.f, 0.f, 0.f, 0.f);
        if (i0 + r < N_) qv = *(const float4*)&Qg[r * 96 + c4 * 4];
        *(float4*)&Qs[r * 100 + c4 * 4] = qv;
    }
    __syncthreads();

    // ---- rel-pos bias dots from Qs ----
    #pragma unroll
    for (int idx = tid; idx < 2304; idx += 256) {
        int r = idx / 36, e = idx - (idx / 36) * 36;
        int i = i0 + r;
        const float* tab = rph;
        float* dst;
        bool valid = (i < N_);
        int it = i / 196;
        int rm = i - it * 196;
        int ih = rm / 14, iw = rm - ih * 14;
        if (e < 14)      { tab = rph + (ih - e + 13) * HD_;        dst = &Rh[r * 14 + e]; }
        else if (e < 28) { int k = e - 14; tab = rpw + (iw - k + 13) * HD_; dst = &Rw[r * 14 + k]; }
        else             { int k = e - 28; tab = rpt + (it - k + 7) * HD_;  dst = &Rt[r * 8 + k]; }
        float s = 0.f;
        if (valid) {
            #pragma unroll 6
            for (int c4 = 0; c4 < 24; c4++) {
                float4 a = *(float4*)&Qs[r * 100 + c4 * 4];
                float4 b = *(const float4*)&tab[c4 * 4];
                s += a.x * b.x + a.y * b.y + a.z * b.z + a.w * b.w;
            }
        }
        *dst = s;
    }

    float lpA = 0.f, lpB = 0.f;              // row-sum partials (rows ra, rb)
    ull accO2[4][3] = {};

    const int ra = 16 * wm + g;              // MMA row pair owned by this thread
    const int rb = ra + 8;
    const float* Kg = g_k + (size_t)bh * N_ * HD_;
    const float* Vg = g_v + (size_t)bh * N_ * HD_;

    for (int ch = 0; ch < 25; ch++) {
        int j0 = ch * 64;
        __syncthreads();
        #pragma unroll
        for (int it = 0; it < 6; it++) {
            int idx = tid + 256 * it;        // 1536 = 64 rows x 24 float4
            int row = idx / 24, c4 = idx % 24;
            int j = j0 + row;
            float4 kv, vv;
            if (j < N_) {
                kv = *(const float4*)&Kg[(size_t)j * 96 + c4 * 4];
                vv = *(const float4*)&Vg[(size_t)j * 96 + c4 * 4];
            } else {
                kv = make_float4(0.f, 0.f, 0.f, 0.f);
                vv = kv;
            }
            // pre-scale + round to tf32 at store (cheap, hides cvt latency)
            uint4 kt;
            kt.x = cvt_tf32(kv.x * SCALE_);
            kt.y = cvt_tf32(kv.y * SCALE_);
            kt.z = cvt_tf32(kv.z * SCALE_);
            kt.w = cvt_tf32(kv.w * SCALE_);
            *(uint4*)&Ks[row * 100 + c4 * 4] = kt;
            *(float4*)&Vs[row * 96  + c4 * 4] = vv;
        }
        __syncthreads();

        // ---- GEMM1: S = Q @ (K*scale)^T via tf32 mma ----
        float c[4][4] = {};                  // [n-tile u][c0..c3]
        const unsigned* Qa = (const unsigned*)Qs;
        const unsigned* Kb = (const unsigned*)Ks;
        #pragma unroll
        for (int k0 = 0; k0 < 96; k0 += 8) {
            unsigned a0 = Qa[ra * 100 + k0 + t];
            unsigned a1 = Qa[rb * 100 + k0 + t];
            unsigned a2 = Qa[ra * 100 + k0 + t + 4];
            unsigned a3 = Qa[rb * 100 + k0 + t + 4];
            #pragma unroll
            for (int u = 0; u < 4; u++) {
                int kr = 32 * wn + 8 * u + g;
                unsigned b0 = Kb[kr * 100 + k0 + t];
                unsigned b1 = Kb[kr * 100 + k0 + t + 4];
                mma_tf32(c[u], a0, a1, a2, a3, b0, b1);
            }
        }

        // ---- bias + exp in C-fragment layout ----
        #pragma unroll
        for (int u = 0; u < 4; u++) {
            int cc = 32 * wn + 8 * u + 2 * t;
            #pragma unroll
            for (int q2 = 0; q2 < 2; q2++) {
                int j = j0 + cc + q2;
                float pA = 0.f, pB = 0.f;
                if (j < N_) {
                    int jt = j / 196;
                    int jr = j - jt * 196;
                    int jh = jr / 14;
                    int jw = jr - jh * 14;
                    pA = __expf(c[u][q2]     + Rt[ra * 8 + jt] + Rh[ra * 14 + jh] + Rw[ra * 14 + jw]);
                    pB = __expf(c[u][q2 + 2] + Rt[rb * 8 + jt] + Rh[rb * 14 + jh] + Rw[rb * 14 + jw]);
                }
                lpA += pA; lpB += pB;
                Ps[ra * 68 + cc + q2] = pA;
                Ps[rb * 68 + cc + q2] = pB;
            }
        }
        __syncthreads();

        // ---- GEMM2: O += P @ V (FFMA2, packed along output cols) ----
        #pragma unroll 4
        for (int j4 = 0; j4 < 16; j4++) {
            float4 p[4];
            #pragma unroll
            for (int rr = 0; rr < 4; rr++)
                p[rr] = *(float4*)&Ps[(y + 16 * rr) * 68 + j4 * 4];
            #pragma unroll
            for (int jj = 0; jj < 4; jj++) {
                const float* vb = &Vs[(j4 * 4 + jj) * 96 + x * 6];
                ull v0 = *(const ull*)(vb + 0);
                ull v1 = *(const ull*)(vb + 2);
                ull v2 = *(const ull*)(vb + 4);
                #pragma unroll
                for (int rr = 0; rr < 4; rr++) {
                    float pv = (jj == 0) ? p[rr].x : (jj == 1) ? p[rr].y
                             : (jj == 2) ? p[rr].z : p[rr].w;
                    ull pd = dup2(pv);
                    fma2(accO2[rr][0], pd, v0);
                    fma2(accO2[rr][1], pd, v1);
                    fma2(accO2[rr][2], pd, v2);
                }
            }
        }
    }

    // ---- row-sum combine: reduce over quad (t), publish per-wn partials ----
    lpA += __shfl_xor_sync(0xffffffffu, lpA, 1);
    lpA += __shfl_xor_sync(0xffffffffu, lpA, 2);
    lpB += __shfl_xor_sync(0xffffffffu, lpB, 1);
    lpB += __shfl_xor_sync(0xffffffffu, lpB, 2);
    if (t == 0) {
        Ls[ra * 2 + wn] = lpA;
        Ls[rb * 2 + wn] = lpB;
    }
    __syncthreads();

    // ---- epilogue: O/l + residual q -> g_ctx ----
    int b = bh >> 2, nh = bh & 3;
    #pragma unroll
    for (int rr = 0; rr < 4; rr++) {
        int r = y + 16 * rr;
        int i = i0 + r;
        if (i >= N_) continue;
        float inv = 1.f / (Ls[r * 2] + Ls[r * 2 + 1]);
        float* dst = &g_ctx[(((size_t)b * N_ + i) * NH_ + nh) * HD_ + x * 6];
        const float* qrow = &Qs[r * 100 + x * 6];
        #pragma unroll
        for (int tp = 0; tp < 3; tp++) {
            float lo, hi;
            unpack2(accO2[rr][tp], lo, hi);
            dst[2 * tp + 0] = lo * inv + qrow[2 * tp + 0];
            dst[2 * tp + 1] = hi * inv + qrow[2 * tp + 1];
        }
    }
}

// ---------------- K4: output projection + bias -----------------------------
__global__ void __launch_bounds__(256, 2) k_proj(const float* __restrict__ proj_w,
                                                 const float* __restrict__ proj_b,
                                                 float* __restrict__ out) {
    int n0 = blockIdx.x * 64, m0 = blockIdx.y * 64;
    int xx = threadIdx.x & 15, yy = threadIdx.x >> 4;
    ull acc2[4][4] = {};
    gemm_nt64(g_ctx, proj_w, DIM_, m0, n0, xx, yy, acc2);
    #pragma unroll
    for (int rr = 0; rr < 4; rr++) {
        int m = m0 + yy + 16 * rr;
        #pragma unroll
        for (int u = 0; u < 4; u++) {
            int o = n0 + xx + 16 * u;
            out[(size_t)m * DIM_ + o] = hadd2(acc2[rr][u]) + proj_b[o];
        }
    }
}

// ---------------- launch ----------------------------------------------------
extern "C" void kernel_launch(void* const* d_in, const int* in_sizes, int n_in,
                              void* d_out, int out_size) {
    const float* x      = (const float*)d_in[0];
    const float* qkv_w  = (const float*)d_in[1];
    const float* proj_w = (const float*)d_in[2];
    const float* proj_b = (const float*)d_in[3];
    const float* pqw    = (const float*)d_in[4];
    const float* pkw    = (const float*)d_in[5];
    const float* pvw    = (const float*)d_in[6];
    const float* nqw    = (const float*)d_in[7];
    const float* nqb    = (const float*)d_in[8];
    const float* nkw    = (const float*)d_in[9];
    const float* nkb    = (const float*)d_in[10];
    const float* nvw    = (const float*)d_in[11];
    const float* nvb    = (const float*)d_in[12];
    const float* rph    = (const float*)d_in[13];
    const float* rpw    = (const float*)d_in[14];
    const float* rpt    = (const float*)d_in[15];
    float* out = (float*)d_out;

    cudaFuncSetAttribute(k_flash, cudaFuncAttributeMaxDynamicSharedMemorySize, 102912);

    k_qkv<<<dim3(18, 49), 256>>>(x, qkv_w);
    k_conv_ln<<<(BH_ * N_ * 3) / 4, 128>>>(pqw, pkw, pvw, nqw, nqb, nkw, nkb, nvw, nvb);
    k_flash<<<dim3(25, BH_), 256, 102912>>>(rph, rpw, rpt);
    k_proj<<<dim3(6, 49), 256>>>(proj_w, proj_b, out);
}

// round 9
// speedup vs baseline: 1.4998x; 1.2671x over previous
#include <cuda_runtime.h>
#include <cuda_bf16.h>
#include <math.h>

#define B_    2
#define NH_   4
#define T_    8
#define H_    14
#define W_    14
#define N_    1568
#define DIM_  384
#define HD_   96
#define BH_   (B_*NH_)
#define M_    (B_*N_)
#define EPS_  1e-6f
#define SCALE_ 0.1020620726159657f   // 96^-0.5

typedef unsigned long long ull;

__device__ __forceinline__ unsigned cvt_tf32(float f) {
    unsigned r;
    asm("cvt.rna.tf32.f32 %0, %1;" : "=r"(r) : "f"(f));
    return r;
}
// tf32 mma m16n8k8: D += A*B, A row-major 16x8, B "col" ([n][k]) 8x8
__device__ __forceinline__ void mma_tf32(float c[4], unsigned a0, unsigned a1,
                                         unsigned a2, unsigned a3,
                                         unsigned b0, unsigned b1) {
    asm("mma.sync.aligned.m16n8k8.row.col.f32.tf32.tf32.f32 "
        "{%0,%1,%2,%3}, {%4,%5,%6,%7}, {%8,%9}, {%0,%1,%2,%3};"
        : "+f"(c[0]), "+f"(c[1]), "+f"(c[2]), "+f"(c[3])
        : "r"(a0), "r"(a1), "r"(a2), "r"(a3), "r"(b0), "r"(b1));
}

// ---------------- scratch ---------------------------------------------------
__device__ float g_q_raw[BH_ * N_ * HD_];
__device__ float g_k_raw[BH_ * N_ * HD_];
__device__ float g_v_raw[BH_ * N_ * HD_];
__device__ float g_q[BH_ * N_ * HD_];
__device__ float g_k[BH_ * N_ * HD_];
__device__ float g_v[BH_ * N_ * HD_];
__device__ float g_ctx[B_ * N_ * DIM_];

// ------- 64x64 NT GEMM core, tf32 MMA, double-buffered smem ----------------
// A [M][K], B [N][K] row-major fp32 in gmem; rna->tf32 at staging.
// 8 warps as 4m x 2n; warp tile 16x32. acc[u][0..3]: rows ra/rb, cols 2t,2t+1.
__device__ __forceinline__ void mma_nt64(const float* __restrict__ A,
                                         const float* __restrict__ Bw,
                                         int K, int m0, int n0,
                                         int wm, int wn, int g, int t,
                                         int tid, float acc[4][4]) {
    __shared__ unsigned Xs[2][64 * 36];
    __shared__ unsigned Ws[2][64 * 36];
    const int r0 = tid >> 3, c40 = tid & 7;
    const int r1 = (tid + 256) >> 3, c41 = tid & 7;
    const int ra = 16 * wm + g;

    float4 pa0 = *(const float4*)&A[(size_t)(m0 + r0) * K + c40 * 4];
    float4 pb0 = *(const float4*)&Bw[(size_t)(n0 + r0) * K + c40 * 4];
    float4 pa1 = *(const float4*)&A[(size_t)(m0 + r1) * K + c41 * 4];
    float4 pb1 = *(const float4*)&Bw[(size_t)(n0 + r1) * K + c41 * 4];
    #define ST_TF32(dst, v) do { uint4 _u; _u.x = cvt_tf32((v).x); _u.y = cvt_tf32((v).y); \
        _u.z = cvt_tf32((v).z); _u.w = cvt_tf32((v).w); *(uint4*)(dst) = _u; } while (0)
    ST_TF32(&Xs[0][r0 * 36 + c40 * 4], pa0);
    ST_TF32(&Ws[0][r0 * 36 + c40 * 4], pb0);
    ST_TF32(&Xs[0][r1 * 36 + c41 * 4], pa1);
    ST_TF32(&Ws[0][r1 * 36 + c41 * 4], pb1);
    __syncthreads();

    int p = 0;
    for (int k0 = 0; k0 < K; k0 += 32) {
        if (k0 + 32 < K) {
            pa0 = *(const float4*)&A[(size_t)(m0 + r0) * K + k0 + 32 + c40 * 4];
            pb0 = *(const float4*)&Bw[(size_t)(n0 + r0) * K + k0 + 32 + c40 * 4];
            pa1 = *(const float4*)&A[(size_t)(m0 + r1) * K + k0 + 32 + c41 * 4];
            pb1 = *(const float4*)&Bw[(size_t)(n0 + r1) * K + k0 + 32 + c41 * 4];
        }
        #pragma unroll
        for (int ks = 0; ks < 4; ks++) {
            int kk = ks * 8;
            unsigned a0 = Xs[p][ra * 36 + kk + t];
            unsigned a1 = Xs[p][(ra + 8) * 36 + kk + t];
            unsigned a2 = Xs[p][ra * 36 + kk + t + 4];
            unsigned a3 = Xs[p][(ra + 8) * 36 + kk + t + 4];
            #pragma unroll
            for (int u = 0; u < 4; u++) {
                int nr = 32 * wn + 8 * u + g;
                unsigned b0 = Ws[p][nr * 36 + kk + t];
                unsigned b1 = Ws[p][nr * 36 + kk + t + 4];
                mma_tf32(acc[u], a0, a1, a2, a3, b0, b1);
            }
        }
        if (k0 + 32 < K) {
            ST_TF32(&Xs[1 - p][r0 * 36 + c40 * 4], pa0);
            ST_TF32(&Ws[1 - p][r0 * 36 + c40 * 4], pb0);
            ST_TF32(&Xs[1 - p][r1 * 36 + c41 * 4], pa1);
            ST_TF32(&Ws[1 - p][r1 * 36 + c41 * 4], pb1);
            __syncthreads();
            p ^= 1;
        }
    }
    #undef ST_TF32
}

// ---------------- K1: QKV projection (tf32 MMA) -----------------------------
__global__ void __launch_bounds__(256, 2) k_qkv(const float* __restrict__ x,
                                                const float* __restrict__ qkv_w) {
    int n0 = blockIdx.x * 64, m0 = blockIdx.y * 64;
    int tid = threadIdx.x;
    int wid = tid >> 5, lane = tid & 31;
    int wm = wid >> 1, wn = wid & 1;
    int g = lane >> 2, t = lane & 3;
    float acc[4][4] = {};
    mma_nt64(x, qkv_w, DIM_, m0, n0, wm, wn, g, t, tid, acc);

    int ra = 16 * wm + g;
    #pragma unroll
    for (int half = 0; half < 2; half++) {
        int m = m0 + ra + 8 * half;
        int b = m / N_, n = m - b * N_;
        #pragma unroll
        for (int u = 0; u < 4; u++) {
            int o = n0 + 32 * wn + 8 * u + 2 * t;
            int s = o / DIM_;
            int rem = o - s * DIM_;
            int head = rem / HD_;
            int c = rem - head * HD_;
            float* dst = (s == 0) ? g_q_raw : (s == 1) ? g_k_raw : g_v_raw;
            float2 v = make_float2(acc[u][2 * half], acc[u][2 * half + 1]);
            *(float2*)&dst[((size_t)(b * NH_ + head) * N_ + n) * HD_ + c] = v;
        }
    }
}

// ---------------- K2: conv3x3x3 + LayerNorm, warp per token ---------------
__global__ void __launch_bounds__(128) k_conv_ln(
        const float* __restrict__ wq, const float* __restrict__ wk,
        const float* __restrict__ wv,
        const float* __restrict__ gq, const float* __restrict__ bq,
        const float* __restrict__ gk, const float* __restrict__ bk,
        const float* __restrict__ gv, const float* __restrict__ bv) {
    int gid = blockIdx.x * 4 + (threadIdx.x >> 5);
    int lane = threadIdx.x & 31;
    int z = gid / (BH_ * N_);
    int rem0 = gid - z * (BH_ * N_);
    int bh = rem0 / N_;
    int n = rem0 - bh * N_;
    const float* inb  = (z == 0) ? g_q_raw : (z == 1) ? g_k_raw : g_v_raw;
    float*       outb = (z == 0) ? g_q     : (z == 1) ? g_k     : g_v;
    const float* wt    = (z == 0) ? wq : (z == 1) ? wk : wv;
    const float* gamma = (z == 0) ? gq : (z == 1) ? gk : gv;
    const float* beta  = (z == 0) ? bq : (z == 1) ? bk : bv;

    int tt = n / (H_ * W_);
    int rem = n - tt * (H_ * W_);
    int hh = rem / W_, ww = rem - (rem / W_) * W_;

    float val[3] = {0.f, 0.f, 0.f};
    #pragma unroll
    for (int dt = -1; dt <= 1; dt++) {
        int t2 = tt + dt;
        if (t2 < 0 || t2 >= T_) continue;
        #pragma unroll
        for (int dh = -1; dh <= 1; dh++) {
            int h2 = hh + dh;
            if (h2 < 0 || h2 >= H_) continue;
            #pragma unroll
            for (int dw = -1; dw <= 1; dw++) {
                int w2 = ww + dw;
                if (w2 < 0 || w2 >= W_) continue;
                int n2 = (t2 * H_ + h2) * W_ + w2;
                const float* src = &inb[((size_t)bh * N_ + n2) * HD_];
                int tap = (dt + 1) * 9 + (dh + 1) * 3 + (dw + 1);
                #pragma unroll
                for (int p = 0; p < 3; p++) {
                    int c = lane + 32 * p;
                    val[p] += wt[c * 27 + tap] * src[c];
                }
            }
        }
    }
    float s = val[0] + val[1] + val[2];
    float q = val[0]*val[0] + val[1]*val[1] + val[2]*val[2];
    #pragma unroll
    for (int o = 16; o; o >>= 1) {
        s += __shfl_xor_sync(0xffffffffu, s, o);
        q += __shfl_xor_sync(0xffffffffu, q, o);
    }
    float mean = s * (1.f / HD_);
    float var  = q * (1.f / HD_) - mean * mean;
    float rstd = rsqrtf(var + EPS_);
    float* dst = &outb[((size_t)bh * N_ + n) * HD_];
    #pragma unroll
    for (int p = 0; p < 3; p++) {
        int c = lane + 32 * p;
        dst[c] = (val[p] - mean) * rstd * gamma[c] + beta[c];
    }
}

// ---------------- K3: flash attention, full tf32 MMA ------------------------
// grid (25, 8). 64 Q rows x 64-key chunks. GEMM1 = QK^T MMA; GEMM2 = P@V MMA
// with V stored transposed (Vt[96][68], tf32). No-max softmax.
__global__ void __launch_bounds__(256, 2) k_flash(const float* __restrict__ rph,
                                                  const float* __restrict__ rpw,
                                                  const float* __restrict__ rpt) {
    extern __shared__ float sm[];
    float*    Qs = sm;              // [64][100] fp32 (residual needs exact q)
    unsigned* Ks = (unsigned*)(sm + 6400);   // [64][100] tf32, pre-scaled
    unsigned* Vt = (unsigned*)(sm + 12800);  // [96][68]  tf32, transposed
    unsigned* Ps = (unsigned*)(sm + 19328);  // [64][68]  tf32
    float*    Rh = sm + 23680;      // [64][14]
    float*    Rw = sm + 24576;      // [64][14]
    float*    Rt = sm + 25472;      // [64][8]
    float*    Ls = sm + 25984;      // [64][2]
    // total 26112 floats = 104448 B

    int bh = blockIdx.y;
    int i0 = blockIdx.x * 64;
    int tid = threadIdx.x;
    int wid = tid >> 5, lane = tid & 31;
    int wm = wid >> 1, wn = wid & 1;
    int g = lane >> 2, t = lane & 3;
    const int ra = 16 * wm + g;
    const int rb = ra + 8;

    const float* Qg = g_q + ((size_t)bh * N_ + i0) * HD_;
    #pragma unroll
    for (int it = 0; it < 6; it++) {
        int idx = tid + 256 * it;            // 1536 = 64 rows x 24 float4
        int r = idx / 24, c4 = idx % 24;
        float4 qv = make_float4(0.f, 0.f, 0.f, 0.f);
        if (i0 + r < N_) qv = *(const float4*)&Qg[r * 96 + c4 * 4];
        *(float4*)&Qs[r * 100 + c4 * 4] = qv;
    }
    __syncthreads();

    // ---- rel-pos bias dots from Qs ----
    #pragma unroll
    for (int idx = tid; idx < 2304; idx += 256) {
        int r = idx / 36, e = idx - (idx / 36) * 36;
        int i = i0 + r;
        const float* tab = rph;
        float* dst;
        bool valid = (i < N_);
        int it = i / 196;
        int rm = i - it * 196;
        int ih = rm / 14, iw = rm - ih * 14;
        if (e < 14)      { tab = rph + (ih - e + 13) * HD_;        dst = &Rh[r * 14 + e]; }
        else if (e < 28) { int k = e - 14; tab = rpw + (iw - k + 13) * HD_; dst = &Rw[r * 14 + k]; }
        else             { int k = e - 28; tab = rpt + (it - k + 7) * HD_;  dst = &Rt[r * 8 + k]; }
        float s = 0.f;
        if (valid) {
            #pragma unroll 6
            for (int c4 = 0; c4 < 24; c4++) {
                float4 a = *(float4*)&Qs[r * 100 + c4 * 4];
                float4 b = *(const float4*)&tab[c4 * 4];
                s += a.x * b.x + a.y * b.y + a.z * b.z + a.w * b.w;
            }
        }
        *dst = s;
    }

    float lpA = 0.f, lpB = 0.f;
    float accO[6][4] = {};                   // [n-tile u][c0..c3], chans 48wn+8u+2t

    const float* Kg = g_k + (size_t)bh * N_ * HD_;
    const float* Vg = g_v + (size_t)bh * N_ * HD_;

    for (int ch = 0; ch < 25; ch++) {
        int j0 = ch * 64;
        __syncthreads();
        #pragma unroll
        for (int it = 0; it < 6; it++) {
            int idx = tid + 256 * it;        // 1536 = 64 rows x 24 float4
            int row = idx / 24, c4 = idx % 24;
            int j = j0 + row;
            float4 kv, vv;
            if (j < N_) {
                kv = *(const float4*)&Kg[(size_t)j * 96 + c4 * 4];
                vv = *(const float4*)&Vg[(size_t)j * 96 + c4 * 4];
            } else {
                kv = make_float4(0.f, 0.f, 0.f, 0.f);
                vv = kv;
            }
            uint4 kt;
            kt.x = cvt_tf32(kv.x * SCALE_);
            kt.y = cvt_tf32(kv.y * SCALE_);
            kt.z = cvt_tf32(kv.z * SCALE_);
            kt.w = cvt_tf32(kv.w * SCALE_);
            *(uint4*)&Ks[row * 100 + c4 * 4] = kt;
            // transposed V store (tf32): Vt[chan][key]
            Vt[(c4 * 4 + 0) * 68 + row] = cvt_tf32(vv.x);
            Vt[(c4 * 4 + 1) * 68 + row] = cvt_tf32(vv.y);
            Vt[(c4 * 4 + 2) * 68 + row] = cvt_tf32(vv.z);
            Vt[(c4 * 4 + 3) * 68 + row] = cvt_tf32(vv.w);
        }
        __syncthreads();

        // ---- GEMM1: S = Q @ (K*scale)^T via tf32 mma ----
        float c[4][4] = {};
        const unsigned* Qa = (const unsigned*)Qs;
        #pragma unroll
        for (int k0 = 0; k0 < 96; k0 += 8) {
            unsigned a0 = Qa[ra * 100 + k0 + t];
            unsigned a1 = Qa[rb * 100 + k0 + t];
            unsigned a2 = Qa[ra * 100 + k0 + t + 4];
            unsigned a3 = Qa[rb * 100 + k0 + t + 4];
            #pragma unroll
            for (int u = 0; u < 4; u++) {
                int kr = 32 * wn + 8 * u + g;
                unsigned b0 = Ks[kr * 100 + k0 + t];
                unsigned b1 = Ks[kr * 100 + k0 + t + 4];
                mma_tf32(c[u], a0, a1, a2, a3, b0, b1);
            }
        }

        // ---- bias + exp in C-fragment layout; P stored tf32-rounded ----
        #pragma unroll
        for (int u = 0; u < 4; u++) {
            int cc = 32 * wn + 8 * u + 2 * t;
            #pragma unroll
            for (int q2 = 0; q2 < 2; q2++) {
                int j = j0 + cc + q2;
                unsigned pAb = 0, pBb = 0;
                if (j < N_) {
                    int jt = j / 196;
                    int jr = j - jt * 196;
                    int jh = jr / 14;
                    int jw = jr - jh * 14;
                    float bias_j = Rt[ra * 8 + jt];   // row-dependent parts split below
                    pAb = cvt_tf32(__expf(c[u][q2]     + bias_j + Rh[ra * 14 + jh] + Rw[ra * 14 + jw]));
                    pBb = cvt_tf32(__expf(c[u][q2 + 2] + Rt[rb * 8 + jt] + Rh[rb * 14 + jh] + Rw[rb * 14 + jw]));
                }
                lpA += __uint_as_float(pAb);
                lpB += __uint_as_float(pBb);
                Ps[ra * 68 + cc + q2] = pAb;
                Ps[rb * 68 + cc + q2] = pBb;
            }
        }
        __syncthreads();

        // ---- GEMM2: O += P @ V via tf32 mma (B = Vt) ----
        #pragma unroll
        for (int k0 = 0; k0 < 64; k0 += 8) {
            unsigned a0 = Ps[ra * 68 + k0 + t];
            unsigned a1 = Ps[rb * 68 + k0 + t];
            unsigned a2 = Ps[ra * 68 + k0 + t + 4];
            unsigned a3 = Ps[rb * 68 + k0 + t + 4];
            #pragma unroll
            for (int u = 0; u < 6; u++) {
                int nr = 48 * wn + 8 * u + g;
                unsigned b0 = Vt[nr * 68 + k0 + t];
                unsigned b1 = Vt[nr * 68 + k0 + t + 4];
                mma_tf32(accO[u], a0, a1, a2, a3, b0, b1);
            }
        }
    }

    // ---- row-sum combine ----
    lpA += __shfl_xor_sync(0xffffffffu, lpA, 1);
    lpA += __shfl_xor_sync(0xffffffffu, lpA, 2);
    lpB += __shfl_xor_sync(0xffffffffu, lpB, 1);
    lpB += __shfl_xor_sync(0xffffffffu, lpB, 2);
    if (t == 0) {
        Ls[ra * 2 + wn] = lpA;
        Ls[rb * 2 + wn] = lpB;
    }
    __syncthreads();

    // ---- epilogue (MMA C layout): O/l + residual q -> g_ctx ----
    int b = bh >> 2, nh = bh & 3;
    #pragma unroll
    for (int half = 0; half < 2; half++) {
        int r = ra + 8 * half;
        int i = i0 + r;
        if (i >= N_) continue;
        float inv = 1.f / (Ls[r * 2] + Ls[r * 2 + 1]);
        float* dst = &g_ctx[(((size_t)b * N_ + i) * NH_ + nh) * HD_];
        #pragma unroll
        for (int u = 0; u < 6; u++) {
            int cc = 48 * wn + 8 * u + 2 * t;
            float2 v;
            v.x = accO[u][2 * half]     * inv + Qs[r * 100 + cc];
            v.y = accO[u][2 * half + 1] * inv + Qs[r * 100 + cc + 1];
            *(float2*)&dst[cc] = v;
        }
    }
}

// ---------------- K4: output projection + bias (tf32 MMA) ------------------
__global__ void __launch_bounds__(256, 2) k_proj(const float* __restrict__ proj_w,
                                                 const float* __restrict__ proj_b,
                                                 float* __restrict__ out) {
    int n0 = blockIdx.x * 64, m0 = blockIdx.y * 64;
    int tid = threadIdx.x;
    int wid = tid >> 5, lane = tid & 31;
    int wm = wid >> 1, wn = wid & 1;
    int g = lane >> 2, t = lane & 3;
    float acc[4][4] = {};
    mma_nt64(g_ctx, proj_w, DIM_, m0, n0, wm, wn, g, t, tid, acc);

    int ra = 16 * wm + g;
    #pragma unroll
    for (int half = 0; half < 2; half++) {
        int m = m0 + ra + 8 * half;
        #pragma unroll
        for (int u = 0; u < 4; u++) {
            int o = n0 + 32 * wn + 8 * u + 2 * t;
            float2 v;
            v.x = acc[u][2 * half]     + proj_b[o];
            v.y = acc[u][2 * half + 1] + proj_b[o + 1];
            *(float2*)&out[(size_t)m * DIM_ + o] = v;
        }
    }
}

// ---------------- launch ----------------------------------------------------
extern "C" void kernel_launch(void* const* d_in, const int* in_sizes, int n_in,
                              void* d_out, int out_size) {
    const float* x      = (const float*)d_in[0];
    const float* qkv_w  = (const float*)d_in[1];
    const float* proj_w = (const float*)d_in[2];
    const float* proj_b = (const float*)d_in[3];
    const float* pqw    = (const float*)d_in[4];
    const float* pkw    = (const float*)d_in[5];
    const float* pvw    = (const float*)d_in[6];
    const float* nqw    = (const float*)d_in[7];
    const float* nqb    = (const float*)d_in[8];
    const float* nkw    = (const float*)d_in[9];
    const float* nkb    = (const float*)d_in[10];
    const float* nvw    = (const float*)d_in[11];
    const float* nvb    = (const float*)d_in[12];
    const float* rph    = (const float*)d_in[13];
    const float* rpw    = (const float*)d_in[14];
    const float* rpt    = (const float*)d_in[15];
    float* out = (float*)d_out;

    cudaFuncSetAttribute(k_flash, cudaFuncAttributeMaxDynamicSharedMemorySize, 104448);

    k_qkv<<<dim3(18, 49), 256>>>(x, qkv_w);
    k_conv_ln<<<(BH_ * N_ * 3) / 4, 128>>>(pqw, pkw, pvw, nqw, nqb, nkw, nkb, nvw, nvb);
    k_flash<<<dim3(25, BH_), 256, 104448>>>(rph, rpw, rpt);
    k_proj<<<dim3(6, 49), 256>>>(proj_w, proj_b, out);
}

// round 10
// speedup vs baseline: 1.6392x; 1.0929x over previous
#include <cuda_runtime.h>
#include <cuda_bf16.h>
#include <math.h>

#define B_    2
#define NH_   4
#define T_    8
#define H_    14
#define W_    14
#define N_    1568
#define DIM_  384
#define HD_   96
#define BH_   (B_*NH_)
#define M_    (B_*N_)
#define EPS_  1e-6f
#define SCALE_ 0.1020620726159657f     // 96^-0.5
#define LOG2E_ 1.4426950408889634f
#define KSC_   0.1472444463f           // SCALE_ * LOG2E_

typedef unsigned long long ull;

__device__ __forceinline__ unsigned cvt_tf32(float f) {
    unsigned r;
    asm("cvt.rna.tf32.f32 %0, %1;" : "=r"(r) : "f"(f));
    return r;
}
__device__ __forceinline__ float ex2f(float x) {
    float r;
    asm("ex2.approx.ftz.f32 %0, %1;" : "=f"(r) : "f"(x));
    return r;
}
// tf32 mma m16n8k8: D += A*B, A row-major 16x8, B "col" ([n][k]) 8x8
__device__ __forceinline__ void mma_tf32(float c[4], unsigned a0, unsigned a1,
                                         unsigned a2, unsigned a3,
                                         unsigned b0, unsigned b1) {
    asm("mma.sync.aligned.m16n8k8.row.col.f32.tf32.tf32.f32 "
        "{%0,%1,%2,%3}, {%4,%5,%6,%7}, {%8,%9}, {%0,%1,%2,%3};"
        : "+f"(c[0]), "+f"(c[1]), "+f"(c[2]), "+f"(c[3])
        : "r"(a0), "r"(a1), "r"(a2), "r"(a3), "r"(b0), "r"(b1));
}

// ---------------- scratch ---------------------------------------------------
__device__ float g_q_raw[BH_ * N_ * HD_];
__device__ float g_k_raw[BH_ * N_ * HD_];
__device__ float g_v_raw[BH_ * N_ * HD_];
__device__ float g_q[BH_ * N_ * HD_];
__device__ float g_k[BH_ * N_ * HD_];
__device__ float g_v[BH_ * N_ * HD_];
__device__ float g_ctx[B_ * N_ * DIM_];

// ------- 64x64 NT GEMM core, tf32 MMA, double-buffered smem ----------------
__device__ __forceinline__ void mma_nt64(const float* __restrict__ A,
                                         const float* __restrict__ Bw,
                                         int K, int m0, int n0,
                                         int wm, int wn, int g, int t,
                                         int tid, float acc[4][4]) {
    __shared__ unsigned Xs[2][64 * 36];
    __shared__ unsigned Ws[2][64 * 36];
    const int r0 = tid >> 3, c40 = tid & 7;
    const int r1 = (tid + 256) >> 3, c41 = tid & 7;
    const int ra = 16 * wm + g;

    float4 pa0 = *(const float4*)&A[(size_t)(m0 + r0) * K + c40 * 4];
    float4 pb0 = *(const float4*)&Bw[(size_t)(n0 + r0) * K + c40 * 4];
    float4 pa1 = *(const float4*)&A[(size_t)(m0 + r1) * K + c41 * 4];
    float4 pb1 = *(const float4*)&Bw[(size_t)(n0 + r1) * K + c41 * 4];
    #define ST_TF32(dst, v) do { uint4 _u; _u.x = cvt_tf32((v).x); _u.y = cvt_tf32((v).y); \
        _u.z = cvt_tf32((v).z); _u.w = cvt_tf32((v).w); *(uint4*)(dst) = _u; } while (0)
    ST_TF32(&Xs[0][r0 * 36 + c40 * 4], pa0);
    ST_TF32(&Ws[0][r0 * 36 + c40 * 4], pb0);
    ST_TF32(&Xs[0][r1 * 36 + c41 * 4], pa1);
    ST_TF32(&Ws[0][r1 * 36 + c41 * 4], pb1);
    __syncthreads();

    int p = 0;
    for (int k0 = 0; k0 < K; k0 += 32) {
        if (k0 + 32 < K) {
            pa0 = *(const float4*)&A[(size_t)(m0 + r0) * K + k0 + 32 + c40 * 4];
            pb0 = *(const float4*)&Bw[(size_t)(n0 + r0) * K + k0 + 32 + c40 * 4];
            pa1 = *(const float4*)&A[(size_t)(m0 + r1) * K + k0 + 32 + c41 * 4];
            pb1 = *(const float4*)&Bw[(size_t)(n0 + r1) * K + k0 + 32 + c41 * 4];
        }
        #pragma unroll
        for (int ks = 0; ks < 4; ks++) {
            int kk = ks * 8;
            unsigned a0 = Xs[p][ra * 36 + kk + t];
            unsigned a1 = Xs[p][(ra + 8) * 36 + kk + t];
            unsigned a2 = Xs[p][ra * 36 + kk + t + 4];
            unsigned a3 = Xs[p][(ra + 8) * 36 + kk + t + 4];
            #pragma unroll
            for (int u = 0; u < 4; u++) {
                int nr = 32 * wn + 8 * u + g;
                unsigned b0 = Ws[p][nr * 36 + kk + t];
                unsigned b1 = Ws[p][nr * 36 + kk + t + 4];
                mma_tf32(acc[u], a0, a1, a2, a3, b0, b1);
            }
        }
        if (k0 + 32 < K) {
            ST_TF32(&Xs[1 - p][r0 * 36 + c40 * 4], pa0);
            ST_TF32(&Ws[1 - p][r0 * 36 + c40 * 4], pb0);
            ST_TF32(&Xs[1 - p][r1 * 36 + c41 * 4], pa1);
            ST_TF32(&Ws[1 - p][r1 * 36 + c41 * 4], pb1);
            __syncthreads();
            p ^= 1;
        }
    }
    #undef ST_TF32
}

// ---------------- K1: QKV projection (tf32 MMA) -----------------------------
__global__ void __launch_bounds__(256, 2) k_qkv(const float* __restrict__ x,
                                                const float* __restrict__ qkv_w) {
    int n0 = blockIdx.x * 64, m0 = blockIdx.y * 64;
    int tid = threadIdx.x;
    int wid = tid >> 5, lane = tid & 31;
    int wm = wid >> 1, wn = wid & 1;
    int g = lane >> 2, t = lane & 3;
    float acc[4][4] = {};
    mma_nt64(x, qkv_w, DIM_, m0, n0, wm, wn, g, t, tid, acc);

    int ra = 16 * wm + g;
    #pragma unroll
    for (int half = 0; half < 2; half++) {
        int m = m0 + ra + 8 * half;
        int b = m / N_, n = m - b * N_;
        #pragma unroll
        for (int u = 0; u < 4; u++) {
            int o = n0 + 32 * wn + 8 * u + 2 * t;
            int s = o / DIM_;
            int rem = o - s * DIM_;
            int head = rem / HD_;
            int c = rem - head * HD_;
            float* dst = (s == 0) ? g_q_raw : (s == 1) ? g_k_raw : g_v_raw;
            float2 v = make_float2(acc[u][2 * half], acc[u][2 * half + 1]);
            *(float2*)&dst[((size_t)(b * NH_ + head) * N_ + n) * HD_ + c] = v;
        }
    }
}

// ---------------- K2: conv3x3x3 + LayerNorm, warp per token ---------------
__global__ void __launch_bounds__(128) k_conv_ln(
        const float* __restrict__ wq, const float* __restrict__ wk,
        const float* __restrict__ wv,
        const float* __restrict__ gq, const float* __restrict__ bq,
        const float* __restrict__ gk, const float* __restrict__ bk,
        const float* __restrict__ gv, const float* __restrict__ bv) {
    int gid = blockIdx.x * 4 + (threadIdx.x >> 5);
    int lane = threadIdx.x & 31;
    int z = gid / (BH_ * N_);
    int rem0 = gid - z * (BH_ * N_);
    int bh = rem0 / N_;
    int n = rem0 - bh * N_;
    const float* inb  = (z == 0) ? g_q_raw : (z == 1) ? g_k_raw : g_v_raw;
    float*       outb = (z == 0) ? g_q     : (z == 1) ? g_k     : g_v;
    const float* wt    = (z == 0) ? wq : (z == 1) ? wk : wv;
    const float* gamma = (z == 0) ? gq : (z == 1) ? gk : gv;
    const float* beta  = (z == 0) ? bq : (z == 1) ? bk : bv;

    int tt = n / (H_ * W_);
    int rem = n - tt * (H_ * W_);
    int hh = rem / W_, ww = rem - (rem / W_) * W_;

    float val[3] = {0.f, 0.f, 0.f};
    #pragma unroll
    for (int dt = -1; dt <= 1; dt++) {
        int t2 = tt + dt;
        if (t2 < 0 || t2 >= T_) continue;
        #pragma unroll
        for (int dh = -1; dh <= 1; dh++) {
            int h2 = hh + dh;
            if (h2 < 0 || h2 >= H_) continue;
            #pragma unroll
            for (int dw = -1; dw <= 1; dw++) {
                int w2 = ww + dw;
                if (w2 < 0 || w2 >= W_) continue;
                int n2 = (t2 * H_ + h2) * W_ + w2;
                const float* src = &inb[((size_t)bh * N_ + n2) * HD_];
                int tap = (dt + 1) * 9 + (dh + 1) * 3 + (dw + 1);
                #pragma unroll
                for (int p = 0; p < 3; p++) {
                    int c = lane + 32 * p;
                    val[p] += wt[c * 27 + tap] * src[c];
                }
            }
        }
    }
    float s = val[0] + val[1] + val[2];
    float q = val[0]*val[0] + val[1]*val[1] + val[2]*val[2];
    #pragma unroll
    for (int o = 16; o; o >>= 1) {
        s += __shfl_xor_sync(0xffffffffu, s, o);
        q += __shfl_xor_sync(0xffffffffu, q, o);
    }
    float mean = s * (1.f / HD_);
    float var  = q * (1.f / HD_) - mean * mean;
    float rstd = rsqrtf(var + EPS_);
    float* dst = &outb[((size_t)bh * N_ + n) * HD_];
    #pragma unroll
    for (int p = 0; p < 3; p++) {
        int c = lane + 32 * p;
        dst[c] = (val[p] - mean) * rstd * gamma[c] + beta[c];
    }
}

// ---------------- K3: flash attention, full tf32 MMA, prefetch -------------
// grid (25, 8). 64 Q rows x 64-key chunks. GEMM1 = QK^T MMA. GEMM2 = P@V MMA
// reading B-fragments straight from row-major V at stride 104 (bank-bijective:
// 104%32=8 -> bank = 8t+g+const). K/V gmem loads software-prefetched into
// registers, issued before GEMM2 of the previous chunk. exp2-folded softmax.
__global__ void __launch_bounds__(256, 2) k_flash(const float* __restrict__ rph,
                                                  const float* __restrict__ rpw,
                                                  const float* __restrict__ rpt) {
    extern __shared__ float sm[];
    float*    Qs = sm;                       // [64][100] fp32
    unsigned* Ks = (unsigned*)(sm + 6400);   // [64][100] tf32, pre-scaled by KSC_
    unsigned* Vs = (unsigned*)(sm + 12800);  // [64][104] tf32 row-major
    unsigned* Ps = (unsigned*)(sm + 19456);  // [64][68]  tf32
    float*    Rh = sm + 23808;               // [64][14]  (x log2e)
    float*    Rw = sm + 24704;               // [64][14]
    float*    Rt = sm + 25600;               // [64][8]
    float*    Ls = sm + 26112;               // [64][2]
    // total 26240 floats = 104960 B

    int bh = blockIdx.y;
    int i0 = blockIdx.x * 64;
    int tid = threadIdx.x;
    int wid = tid >> 5, lane = tid & 31;
    int wm = wid >> 1, wn = wid & 1;
    int g = lane >> 2, t = lane & 3;
    const int ra = 16 * wm + g;
    const int rb = ra + 8;

    const float* Qg = g_q + ((size_t)bh * N_ + i0) * HD_;
    #pragma unroll
    for (int it = 0; it < 6; it++) {
        int idx = tid + 256 * it;
        int r = idx / 24, c4 = idx % 24;
        float4 qv = make_float4(0.f, 0.f, 0.f, 0.f);
        if (i0 + r < N_) qv = *(const float4*)&Qg[r * 96 + c4 * 4];
        *(float4*)&Qs[r * 100 + c4 * 4] = qv;
    }
    __syncthreads();

    // ---- rel-pos bias dots from Qs (scaled by log2e for exp2 softmax) ----
    #pragma unroll
    for (int idx = tid; idx < 2304; idx += 256) {
        int r = idx / 36, e = idx - (idx / 36) * 36;
        int i = i0 + r;
        const float* tab = rph;
        float* dst;
        bool valid = (i < N_);
        int it = i / 196;
        int rm = i - it * 196;
        int ih = rm / 14, iw = rm - ih * 14;
        if (e < 14)      { tab = rph + (ih - e + 13) * HD_;        dst = &Rh[r * 14 + e]; }
        else if (e < 28) { int k = e - 14; tab = rpw + (iw - k + 13) * HD_; dst = &Rw[r * 14 + k]; }
        else             { int k = e - 28; tab = rpt + (it - k + 7) * HD_;  dst = &Rt[r * 8 + k]; }
        float s = 0.f;
        if (valid) {
            #pragma unroll 6
            for (int c4 = 0; c4 < 24; c4++) {
                float4 a = *(float4*)&Qs[r * 100 + c4 * 4];
                float4 b = *(const float4*)&tab[c4 * 4];
                s += a.x * b.x + a.y * b.y + a.z * b.z + a.w * b.w;
            }
        }
        *dst = s * LOG2E_;
    }

    float lpA = 0.f, lpB = 0.f;
    float accO[6][4] = {};

    const float* Kg = g_k + (size_t)bh * N_ * HD_;
    const float* Vg = g_v + (size_t)bh * N_ * HD_;

    // staging-row constants per thread
    int srow[6], sc4[6];
    #pragma unroll
    for (int it = 0; it < 6; it++) {
        int idx = tid + 256 * it;
        srow[it] = idx / 24;
        sc4[it]  = idx % 24;
    }

    float4 kReg[6], vReg[6];
    // prefetch chunk 0
    #pragma unroll
    for (int it = 0; it < 6; it++) {
        int j = srow[it];
        if (j < N_) {
            kReg[it] = *(const float4*)&Kg[(size_t)j * 96 + sc4[it] * 4];
            vReg[it] = *(const float4*)&Vg[(size_t)j * 96 + sc4[it] * 4];
        } else {
            kReg[it] = make_float4(0.f, 0.f, 0.f, 0.f);
            vReg[it] = kReg[it];
        }
    }

    for (int ch = 0; ch < 25; ch++) {
        int j0 = ch * 64;
        __syncthreads();                     // Ks/Vs free (prev GEMM2 done)
        #pragma unroll
        for (int it = 0; it < 6; it++) {
            int row = srow[it], c4 = sc4[it];
            uint4 kt;
            kt.x = cvt_tf32(kReg[it].x * KSC_);
            kt.y = cvt_tf32(kReg[it].y * KSC_);
            kt.z = cvt_tf32(kReg[it].z * KSC_);
            kt.w = cvt_tf32(kReg[it].w * KSC_);
            *(uint4*)&Ks[row * 100 + c4 * 4] = kt;
            uint4 vt;
            vt.x = cvt_tf32(vReg[it].x);
            vt.y = cvt_tf32(vReg[it].y);
            vt.z = cvt_tf32(vReg[it].z);
            vt.w = cvt_tf32(vReg[it].w);
            *(uint4*)&Vs[row * 104 + c4 * 4] = vt;
        }
        __syncthreads();

        // ---- GEMM1: S = Q @ (K*ksc)^T via tf32 mma ----
        float c[4][4] = {};
        const unsigned* Qa = (const unsigned*)Qs;
        #pragma unroll
        for (int k0 = 0; k0 < 96; k0 += 8) {
            unsigned a0 = Qa[ra * 100 + k0 + t];
            unsigned a1 = Qa[rb * 100 + k0 + t];
            unsigned a2 = Qa[ra * 100 + k0 + t + 4];
            unsigned a3 = Qa[rb * 100 + k0 + t + 4];
            #pragma unroll
            for (int u = 0; u < 4; u++) {
                int kr = 32 * wn + 8 * u + g;
                unsigned b0 = Ks[kr * 100 + k0 + t];
                unsigned b1 = Ks[kr * 100 + k0 + t + 4];
                mma_tf32(c[u], a0, a1, a2, a3, b0, b1);
            }
        }

        // ---- bias + exp2 in C-fragment layout; P stored tf32 ----
        #pragma unroll
        for (int u = 0; u < 4; u++) {
            int cc = 32 * wn + 8 * u + 2 * t;
            #pragma unroll
            for (int q2 = 0; q2 < 2; q2++) {
                int j = j0 + cc + q2;
                unsigned pAb = 0, pBb = 0;
                if (j < N_) {
                    int jt = j / 196;
                    int jr = j - jt * 196;
                    int jh = jr / 14;
                    int jw = jr - jh * 14;
                    pAb = cvt_tf32(ex2f(c[u][q2]     + Rt[ra * 8 + jt] + Rh[ra * 14 + jh] + Rw[ra * 14 + jw]));
                    pBb = cvt_tf32(ex2f(c[u][q2 + 2] + Rt[rb * 8 + jt] + Rh[rb * 14 + jh] + Rw[rb * 14 + jw]));
                }
                lpA += __uint_as_float(pAb);
                lpB += __uint_as_float(pBb);
                Ps[ra * 68 + cc + q2] = pAb;
                Ps[rb * 68 + cc + q2] = pBb;
            }
        }

        // ---- prefetch next chunk (latency hides behind barrier + GEMM2) ----
        if (ch < 24) {
            int nj0 = j0 + 64;
            #pragma unroll
            for (int it = 0; it < 6; it++) {
                int j = nj0 + srow[it];
                if (j < N_) {
                    kReg[it] = *(const float4*)&Kg[(size_t)j * 96 + sc4[it] * 4];
                    vReg[it] = *(const float4*)&Vg[(size_t)j * 96 + sc4[it] * 4];
                } else {
                    kReg[it] = make_float4(0.f, 0.f, 0.f, 0.f);
                    vReg[it] = kReg[it];
                }
            }
        }
        __syncthreads();

        // ---- GEMM2: O += P @ V via tf32 mma (B read from row-major Vs) ----
        #pragma unroll
        for (int k0 = 0; k0 < 64; k0 += 8) {
            unsigned a0 = Ps[ra * 68 + k0 + t];
            unsigned a1 = Ps[rb * 68 + k0 + t];
            unsigned a2 = Ps[ra * 68 + k0 + t + 4];
            unsigned a3 = Ps[rb * 68 + k0 + t + 4];
            #pragma unroll
            for (int u = 0; u < 6; u++) {
                int nr = 48 * wn + 8 * u + g;
                unsigned b0 = Vs[(k0 + t) * 104 + nr];
                unsigned b1 = Vs[(k0 + t + 4) * 104 + nr];
                mma_tf32(accO[u], a0, a1, a2, a3, b0, b1);
            }
        }
    }

    // ---- row-sum combine ----
    lpA += __shfl_xor_sync(0xffffffffu, lpA, 1);
    lpA += __shfl_xor_sync(0xffffffffu, lpA, 2);
    lpB += __shfl_xor_sync(0xffffffffu, lpB, 1);
    lpB += __shfl_xor_sync(0xffffffffu, lpB, 2);
    if (t == 0) {
        Ls[ra * 2 + wn] = lpA;
        Ls[rb * 2 + wn] = lpB;
    }
    __syncthreads();

    // ---- epilogue (MMA C layout): O/l + residual q -> g_ctx ----
    int b = bh >> 2, nh = bh & 3;
    #pragma unroll
    for (int half = 0; half < 2; half++) {
        int r = ra + 8 * half;
        int i = i0 + r;
        if (i >= N_) continue;
        float inv = 1.f / (Ls[r * 2] + Ls[r * 2 + 1]);
        float* dst = &g_ctx[(((size_t)b * N_ + i) * NH_ + nh) * HD_];
        #pragma unroll
        for (int u = 0; u < 6; u++) {
            int cc = 48 * wn + 8 * u + 2 * t;
            float2 v;
            v.x = accO[u][2 * half]     * inv + Qs[r * 100 + cc];
            v.y = accO[u][2 * half + 1] * inv + Qs[r * 100 + cc + 1];
            *(float2*)&dst[cc] = v;
        }
    }
}

// ---------------- K4: output projection + bias (tf32 MMA) ------------------
__global__ void __launch_bounds__(256, 2) k_proj(const float* __restrict__ proj_w,
                                                 const float* __restrict__ proj_b,
                                                 float* __restrict__ out) {
    int n0 = blockIdx.x * 64, m0 = blockIdx.y * 64;
    int tid = threadIdx.x;
    int wid = tid >> 5, lane = tid & 31;
    int wm = wid >> 1, wn = wid & 1;
    int g = lane >> 2, t = lane & 3;
    float acc[4][4] = {};
    mma_nt64(g_ctx, proj_w, DIM_, m0, n0, wm, wn, g, t, tid, acc);

    int ra = 16 * wm + g;
    #pragma unroll
    for (int half = 0; half < 2; half++) {
        int m = m0 + ra + 8 * half;
        #pragma unroll
        for (int u = 0; u < 4; u++) {
            int o = n0 + 32 * wn + 8 * u + 2 * t;
            float2 v;
            v.x = acc[u][2 * half]     + proj_b[o];
            v.y = acc[u][2 * half + 1] + proj_b[o + 1];
            *(float2*)&out[(size_t)m * DIM_ + o] = v;
        }
    }
}

// ---------------- launch ----------------------------------------------------
extern "C" void kernel_launch(void* const* d_in, const int* in_sizes, int n_in,
                              void* d_out, int out_size) {
    const float* x      = (const float*)d_in[0];
    const float* qkv_w  = (const float*)d_in[1];
    const float* proj_w = (const float*)d_in[2];
    const float* proj_b = (const float*)d_in[3];
    const float* pqw    = (const float*)d_in[4];
    const float* pkw    = (const float*)d_in[5];
    const float* pvw    = (const float*)d_in[6];
    const float* nqw    = (const float*)d_in[7];
    const float* nqb    = (const float*)d_in[8];
    const float* nkw    = (const float*)d_in[9];
    const float* nkb    = (const float*)d_in[10];
    const float* nvw    = (const float*)d_in[11];
    const float* nvb    = (const float*)d_in[12];
    const float* rph    = (const float*)d_in[13];
    const float* rpw    = (const float*)d_in[14];
    const float* rpt    = (const float*)d_in[15];
    float* out = (float*)d_out;

    cudaFuncSetAttribute(k_flash, cudaFuncAttributeMaxDynamicSharedMemorySize, 104960);

    k_qkv<<<dim3(18, 49), 256>>>(x, qkv_w);
    k_conv_ln<<<(BH_ * N_ * 3) / 4, 128>>>(pqw, pkw, pvw, nqw, nqb, nkw, nkb, nvw, nvb);
    k_flash<<<dim3(25, BH_), 256, 104960>>>(rph, rpw, rpt);
    k_proj<<<dim3(6, 49), 256>>>(proj_w, proj_b, out);
}